// round 4
// baseline (speedup 1.0000x reference)
#include <cuda_runtime.h>
#include <cuda_bf16.h>
#include <cstdint>

// Problem constants: T=32768, E=256, K=8, D=8, r=2
#define E_EXPERTS 256
#define D_DEVS    8
#define K_TOPK    8
#define E_PER_DEV (E_EXPERTS / D_DEVS)   // 32

__device__ int g_invperm[E_EXPERTS];

// ---------------------------------------------------------------------------
// Kernel A: zero-fill the entire output with STG.128.
// Block 0 additionally computes the expert->slot permutation table.
// ---------------------------------------------------------------------------
__global__ __launch_bounds__(256) void fill_kernel(
    float4* __restrict__ out4, int n4,
    const int* __restrict__ mapping /* [E, D] one-hot */)
{
    // --- invperm on block 0 (warp-ballot rank; ~200 cycles) ---
    if (blockIdx.x == 0) {
        __shared__ int wcnt[8][8];
        const int e    = threadIdx.x;      // 256 threads
        const int lane = e & 31;
        const int w    = e >> 5;

        int best = mapping[e * D_DEVS];
        int d = 0;
#pragma unroll
        for (int i = 1; i < D_DEVS; i++) {
            int v = mapping[e * D_DEVS + i];
            if (v > best) { best = v; d = i; }
        }

        const unsigned lt = (1u << lane) - 1u;
        int within = 0, mycnt = 0;
#pragma unroll
        for (int d2 = 0; d2 < D_DEVS; d2++) {
            unsigned b = __ballot_sync(0xffffffffu, d == d2);
            if (d2 == d)    within = __popc(b & lt);
            if (lane == d2) mycnt  = __popc(b);
        }
        if (lane < D_DEVS) wcnt[w][lane] = mycnt;
        __syncthreads();

        int off = 0;
#pragma unroll
        for (int w2 = 0; w2 < 8; w2++)
#pragma unroll
            for (int d2 = 0; d2 < D_DEVS; d2++) {
                int c = wcnt[w2][d2];
                off += ((d2 < d) || (d2 == d && w2 < w)) ? c : 0;
            }
        g_invperm[e] = off + within;
    }

    // --- streaming zero-fill (all blocks) ---
    const float4 z = make_float4(0.f, 0.f, 0.f, 0.f);
    const int stride = gridDim.x * blockDim.x;
    for (int i = blockIdx.x * blockDim.x + threadIdx.x; i < n4; i += stride)
        out4[i] = z;
}

// ---------------------------------------------------------------------------
// Kernel B: gather selected scores, scatter STG.32 into the zeroed output,
// write dispatch-mask rows. One warp = 4 tokens (2 reduction pairs);
// all 32 lanes carry one selection each.
// ---------------------------------------------------------------------------
__global__ __launch_bounds__(256) void scatter_kernel(
    const float* __restrict__ topk,   // [T, E]
    const int*   __restrict__ meta,   // [T, K]
    float*       __restrict__ out,    // [D, T, 32]
    float*       __restrict__ mask,   // [T/2, D] as float 0/1
    int T)
{
    const int lane = threadIdx.x & 31;
    const int warp = threadIdx.x >> 5;
    const int quad = blockIdx.x * 8 + warp;     // group of 4 tokens
    const int t0   = quad << 2;

    // 32 contiguous meta ints -> one selection per lane
    const int e    = meta[t0 * K_TOPK + lane];
    const int tokl = lane >> 3;                          // local token 0..3
    const float v  = topk[(t0 + tokl) * E_EXPERTS + e];  // gather (<=32 sectors)
    const int p    = g_invperm[e];                       // slot 0..255 (L1-hot)

    const int d = p >> 5;          // device
    const int j = p & 31;          // device-local slot

    // scattered 4B store into pre-zeroed output (duplicates write same value)
    out[d * (T * E_PER_DEV) + (t0 + tokl) * E_PER_DEV + j] = v;

    // pair masks: OR within each 16-lane half (tokens {0,1} | {2,3})
    unsigned mbits = 1u << d;
#pragma unroll
    for (int off = 8; off; off >>= 1)
        mbits |= __shfl_xor_sync(0xffffffffu, mbits, off);

    const int pair0 = quad << 1;
    if (lane < D_DEVS)
        mask[pair0 * D_DEVS + lane] = ((mbits >> lane) & 1u) ? 1.0f : 0.0f;
    else if (lane >= 16 && lane < 16 + D_DEVS)
        mask[(pair0 + 1) * D_DEVS + (lane & 7)] = ((mbits >> (lane & 7)) & 1u) ? 1.0f : 0.0f;
}

extern "C" void kernel_launch(void* const* d_in, const int* in_sizes, int n_in,
                              void* d_out, int out_size) {
    const float* topk    = (const float*)d_in[0];   // [1,1,T,E]
    const int*   mapping = (const int*)  d_in[1];   // [1,1,E,D]
    const int*   meta    = (const int*)  d_in[2];   // [1,1,T,K]

    const int T = in_sizes[0] / E_EXPERTS;          // 32768

    float* out  = (float*)d_out;                            // [D, T, 32]
    float* mask = out + (size_t)D_DEVS * T * E_PER_DEV;     // [T/2, D]

    // Kernel A: zero remapped region only (mask rows fully written by B).
    const int n4 = (D_DEVS * T * E_PER_DEV) / 4;            // 2M float4
    // 148 SMs * 8 blocks resident; 2368 blocks -> ~886 f4/ thread-equiv
    fill_kernel<<<2368, 256>>>((float4*)out, n4, mapping);

    // Kernel B: scatter + mask
    const int quads  = T >> 2;                       // 8192
    scatter_kernel<<<quads / 8, 256>>>(topk, meta, out, mask, T);
}